// round 8
// baseline (speedup 1.0000x reference)
#include <cuda_runtime.h>
#include <cstdint>

// IPLayer segment-sum: out[atom][g] += inter[pair][g] for atom = ind_2[pair][0]
// Inputs (metadata order): ind_2 (int32, N_PAIRS*2), prop (float32, N_ATOMS*128),
//                          inter (float32, N_PAIRS*64). Output: float32 N_ATOMS*64.

#define N_INTER 64
#define F4_PER_ROW (N_INTER / 4)   // 16
#define PAIRS_PER_WARP 16          // 2 half-warps x 8 pairs each

__global__ void zero_out_kernel(float4* __restrict__ out, int n4) {
    int i = blockIdx.x * blockDim.x + threadIdx.x;
    if (i < n4) out[i] = make_float4(0.f, 0.f, 0.f, 0.f);
}

// Warp layout: lane = h*16 + c, c = float4 chunk (0..15), h = half (0..1).
// The warp owns 16 consecutive pairs; half h handles pairs pbase+h*8 .. +h*8+7.
// Indices for all 16 pairs are loaded by lanes 0..15 in ONE LDG instruction
// and broadcast via shfl. Each thread then issues 8 independent float4 loads
// (MLP=8) and 8 red.global.add.v4.f32; every LDG.128 / RED.128 warp
// instruction covers two fully dense 256B rows.
__global__ void __launch_bounds__(256) seg_red_kernel(
        const int* __restrict__ ind2,
        const float4* __restrict__ inter,
        float* __restrict__ out,
        int n_pairs) {
    int tid  = blockIdx.x * blockDim.x + threadIdx.x;
    int warp = tid >> 5;
    int lane = tid & 31;
    int pbase = warp * PAIRS_PER_WARP;
    if (pbase >= n_pairs) return;

    int c = lane & 15;
    int h = lane >> 4;

    if (pbase + PAIRS_PER_WARP <= n_pairs) {
        // One coalesced index LDG for the warp's 16 pairs.
        int a_mine = 0;
        if (lane < 16) a_mine = __ldg(&ind2[2 * (pbase + lane)]);

        // 8 independent row loads (front-batched by ptxas -> MLP=8).
        const float4* src = inter + (size_t)(pbase + h * 8) * F4_PER_ROW + c;
        float4 v[8];
#pragma unroll
        for (int j = 0; j < 8; j++)
            v[j] = src[(size_t)j * F4_PER_ROW];

        int aj[8];
#pragma unroll
        for (int j = 0; j < 8; j++)
            aj[j] = __shfl_sync(0xFFFFFFFFu, a_mine, h * 8 + j);

#pragma unroll
        for (int j = 0; j < 8; j++) {
            float* dst = out + (size_t)aj[j] * N_INTER + c * 4;
            asm volatile("red.global.add.v4.f32 [%0], {%1,%2,%3,%4};"
                         :: "l"(dst), "f"(v[j].x), "f"(v[j].y), "f"(v[j].z), "f"(v[j].w)
                         : "memory");
        }
    } else {
        // Tail (rare): half 0's 16 lanes process remaining pairs one at a time.
        if (h == 0) {
            for (int p = pbase; p < n_pairs; p++) {
                int a = __ldg(&ind2[2 * p]);
                float4 v = inter[(size_t)p * F4_PER_ROW + c];
                float* dst = out + (size_t)a * N_INTER + c * 4;
                asm volatile("red.global.add.v4.f32 [%0], {%1,%2,%3,%4};"
                             :: "l"(dst), "f"(v.x), "f"(v.y), "f"(v.z), "f"(v.w)
                             : "memory");
            }
        }
    }
}

extern "C" void kernel_launch(void* const* d_in, const int* in_sizes, int n_in,
                              void* d_out, int out_size) {
    const int*    ind2  = (const int*)d_in[0];
    const float4* inter = (const float4*)d_in[2];
    float*        out   = (float*)d_out;

    int n_pairs = in_sizes[0] / 2;

    // Zero the (poisoned) output buffer.
    int n4 = out_size / 4;
    zero_out_kernel<<<(n4 + 255) / 256, 256>>>((float4*)out, n4);

    // 1 warp per 16 pairs; 8 warps (128 pairs) per 256-thread block.
    int n_warps  = (n_pairs + PAIRS_PER_WARP - 1) / PAIRS_PER_WARP;
    int n_blocks = (n_warps + 7) / 8;
    seg_red_kernel<<<n_blocks, 256>>>(ind2, inter, out, n_pairs);
}